// round 3
// baseline (speedup 1.0000x reference)
#include <cuda_runtime.h>
#include <cstdint>
#include <math.h>

#define LSEQ 4096
#define HDIM 512

// ---------------- scratch (__device__ globals; no allocation allowed) ----------------
__device__ float d_gi[2][(size_t)LSEQ * 1536];            // precomputed input gates, per dir
__device__ unsigned long long d_hx[2][HDIM];              // tagged h state: (step<<32)|float_bits
__device__ float d_outcat[(size_t)LSEQ * 1024];           // [out_f | out_b]
__device__ float d_U1[(size_t)LSEQ * 9216];               // KAN1 augmented input
__device__ float d_V1[(size_t)HDIM * 9216];               // KAN1 augmented weight
__device__ float d_U2[(size_t)LSEQ * 4608];               // KAN2 augmented input
__device__ float d_V2[(size_t)HDIM * 4608];               // KAN2 augmented weight
__device__ float d_a2[(size_t)LSEQ * HDIM];               // KAN2 output

// ---------------- init ----------------
__global__ void init_kernel() {
    int t = blockIdx.x * blockDim.x + threadIdx.x;
    if (t < 2 * HDIM) ((unsigned long long*)d_hx)[t] = 0ull;
}

// ---------------- packed f32x2 helpers ----------------
__device__ __forceinline__ unsigned long long pack2f(float x, float y) {
    unsigned long long r;
    asm("mov.b64 %0, {%1, %2};" : "=l"(r) : "f"(x), "f"(y));
    return r;
}
__device__ __forceinline__ void unpack2f(unsigned long long v, float& x, float& y) {
    asm("mov.b64 {%0, %1}, %2;" : "=f"(x), "=f"(y) : "l"(v));
}
#define FMA2(d, a, b) asm("fma.rn.f32x2 %0, %1, %2, %0;" : "+l"(d) : "l"(a), "l"(b))

// ---------------- SGEMM: C[M,N] = act(A[M,K] @ B[N,K]^T + bias[N]) ----------------
// 128x128 block, BK=16, 256 threads, 8x8 per thread via packed f32x2 diagonal scheme.
// act: 0=none, 1=relu, 2=sigmoid
__global__ __launch_bounds__(256, 2) void sgemm_kernel(
    const float* __restrict__ A, const float* __restrict__ B,
    const float* __restrict__ bias, float* __restrict__ C,
    int M, int N, int K, int act)
{
    __shared__ float As[16][128];
    __shared__ float Bs[16][128];
    __shared__ float Bw[16][128];   // pair-swapped copy of Bs along n
    int tid = threadIdx.x;
    int tx = tid & 15, ty = tid >> 4;
    const float* Ablk = A + (size_t)blockIdx.y * 128 * K;
    const float* Bblk = B + (size_t)blockIdx.x * 128 * K;

    int r0 = tid >> 2;            // 0..63
    int c0 = (tid & 3) * 4;       // 0,4,8,12

    unsigned long long P[4][4], Q[4][4];
    unsigned long long zz = pack2f(0.f, 0.f);
#pragma unroll
    for (int i = 0; i < 4; i++)
#pragma unroll
        for (int j = 0; j < 4; j++) { P[i][j] = zz; Q[i][j] = zz; }

    // prefetch first tile
    float4 pa0 = *(const float4*)(Ablk + (size_t)r0 * K + c0);
    float4 pa1 = *(const float4*)(Ablk + (size_t)(r0 + 64) * K + c0);
    float4 pb0 = *(const float4*)(Bblk + (size_t)r0 * K + c0);
    float4 pb1 = *(const float4*)(Bblk + (size_t)(r0 + 64) * K + c0);

    for (int k0 = 0; k0 < K; k0 += 16) {
        // store prefetched tile to smem (A/B transposed to [k][row]; Bw pair-swapped rows)
        As[c0 + 0][r0] = pa0.x; As[c0 + 1][r0] = pa0.y; As[c0 + 2][r0] = pa0.z; As[c0 + 3][r0] = pa0.w;
        As[c0 + 0][r0 + 64] = pa1.x; As[c0 + 1][r0 + 64] = pa1.y; As[c0 + 2][r0 + 64] = pa1.z; As[c0 + 3][r0 + 64] = pa1.w;
        Bs[c0 + 0][r0] = pb0.x; Bs[c0 + 1][r0] = pb0.y; Bs[c0 + 2][r0] = pb0.z; Bs[c0 + 3][r0] = pb0.w;
        Bs[c0 + 0][r0 + 64] = pb1.x; Bs[c0 + 1][r0 + 64] = pb1.y; Bs[c0 + 2][r0 + 64] = pb1.z; Bs[c0 + 3][r0 + 64] = pb1.w;
        int rs0 = r0 ^ 1, rs1 = (r0 + 64) ^ 1;
        Bw[c0 + 0][rs0] = pb0.x; Bw[c0 + 1][rs0] = pb0.y; Bw[c0 + 2][rs0] = pb0.z; Bw[c0 + 3][rs0] = pb0.w;
        Bw[c0 + 0][rs1] = pb1.x; Bw[c0 + 1][rs1] = pb1.y; Bw[c0 + 2][rs1] = pb1.z; Bw[c0 + 3][rs1] = pb1.w;
        __syncthreads();

        // prefetch next tile
        if (k0 + 16 < K) {
            pa0 = *(const float4*)(Ablk + (size_t)r0 * K + k0 + 16 + c0);
            pa1 = *(const float4*)(Ablk + (size_t)(r0 + 64) * K + k0 + 16 + c0);
            pb0 = *(const float4*)(Bblk + (size_t)r0 * K + k0 + 16 + c0);
            pb1 = *(const float4*)(Bblk + (size_t)(r0 + 64) * K + k0 + 16 + c0);
        }

#pragma unroll
        for (int k = 0; k < 16; k++) {
            float4 av0 = *(const float4*)&As[k][ty * 8];
            float4 av1 = *(const float4*)&As[k][ty * 8 + 4];
            float4 bv0 = *(const float4*)&Bs[k][tx * 8];
            float4 bv1 = *(const float4*)&Bs[k][tx * 8 + 4];
            float4 wv0 = *(const float4*)&Bw[k][tx * 8];
            float4 wv1 = *(const float4*)&Bw[k][tx * 8 + 4];
            unsigned long long ap[4], bp[4], wp[4];
            ap[0] = pack2f(av0.x, av0.y); ap[1] = pack2f(av0.z, av0.w);
            ap[2] = pack2f(av1.x, av1.y); ap[3] = pack2f(av1.z, av1.w);
            bp[0] = pack2f(bv0.x, bv0.y); bp[1] = pack2f(bv0.z, bv0.w);
            bp[2] = pack2f(bv1.x, bv1.y); bp[3] = pack2f(bv1.z, bv1.w);
            wp[0] = pack2f(wv0.x, wv0.y); wp[1] = pack2f(wv0.z, wv0.w);
            wp[2] = pack2f(wv1.x, wv1.y); wp[3] = pack2f(wv1.z, wv1.w);
#pragma unroll
            for (int ii = 0; ii < 4; ii++)
#pragma unroll
                for (int jj = 0; jj < 4; jj++) {
                    FMA2(P[ii][jj], ap[ii], bp[jj]);
                    FMA2(Q[ii][jj], ap[ii], wp[jj]);
                }
        }
        __syncthreads();
    }

    // unpack diagonal accumulators into acc[i][j]
    float acc[8][8];
#pragma unroll
    for (int ii = 0; ii < 4; ii++)
#pragma unroll
        for (int jj = 0; jj < 4; jj++) {
            float px, py, qx, qy;
            unpack2f(P[ii][jj], px, py);
            unpack2f(Q[ii][jj], qx, qy);
            acc[2 * ii][2 * jj] = px;         // (2ii, 2jj)
            acc[2 * ii + 1][2 * jj + 1] = py; // (2ii+1, 2jj+1)
            acc[2 * ii][2 * jj + 1] = qx;     // (2ii, 2jj+1)
            acc[2 * ii + 1][2 * jj] = qy;     // (2ii+1, 2jj)
        }

    int nbase = blockIdx.x * 128 + tx * 8;
    int mbase = blockIdx.y * 128 + ty * 8;
#pragma unroll
    for (int i = 0; i < 8; i++) {
#pragma unroll
        for (int j = 0; j < 8; j++) {
            float v = acc[i][j];
            if (bias) v += bias[nbase + j];
            if (act == 1) v = fmaxf(v, 0.f);
            else if (act == 2) v = 1.f / (1.f + expf(-v));
            acc[i][j] = v;
        }
        float4* dst = (float4*)(C + (size_t)(mbase + i) * N + nbase);
        dst[0] = make_float4(acc[i][0], acc[i][1], acc[i][2], acc[i][3]);
        dst[1] = make_float4(acc[i][4], acc[i][5], acc[i][6], acc[i][7]);
    }
}

// ---------------- persistent bidirectional GRU recurrence ----------------
// 64 CTAs per direction (128 total, co-resident), 384 threads each.
// Each CTA owns 8 outputs -> 24 dots of length 512; 16 threads per dot (32 h each).
// h exchanged via self-tagged 64-bit words: (step<<32)|float_bits — no fence, no barrier.
#define GCTAS 64
#define GOUT 8
#define GTH 384

__global__ __launch_bounds__(GTH, 1) void gru_kernel(
    const float* __restrict__ whh_f, const float* __restrict__ bhh_f,
    const float* __restrict__ whh_b, const float* __restrict__ bhh_b)
{
    int cta = blockIdx.x;
    int dir = (cta >= GCTAS) ? 1 : 0;
    int slice = cta - dir * GCTAS;
    const float* whh = dir ? whh_b : whh_f;
    const float* bhh = dir ? bhh_b : bhh_f;
    const float* gibase = d_gi[dir];
    unsigned long long* hx = d_hx[dir];

    int tid = threadIdx.x;
    int dot = tid >> 4;           // 0..23
    int lane = tid & 15;
    int gate = dot >> 3;          // 0..2
    int jl = dot & 7;             // 0..7
    int jg = slice * GOUT + jl;   // global output index

    // weights for this thread: h[lane*32 .. lane*32+32)
    float4 w[8];
    {
        const float4* wr = (const float4*)(whh + (size_t)(gate * HDIM + jg) * HDIM + lane * 32);
#pragma unroll
        for (int i = 0; i < 8; i++) w[i] = wr[i];
    }
    float myb = bhh[gate * HDIM + jg];

    __shared__ float h_sh[HDIM];
    __shared__ float s_sum[24];
    __shared__ float s_gi[24];

    for (int i = tid; i < HDIM; i += GTH) h_sh[i] = 0.f;
    float hprev = 0.f;            // valid for tid < GOUT
    __syncthreads();

    for (int s = 0; s < LSEQ; s++) {
        int t = dir ? (LSEQ - 1 - s) : s;

        // gi prefetch by dot leaders (independent of h wait -> overlaps the spin)
        float giv = 0.f;
        if (lane == 0) giv = __ldg(gibase + (size_t)t * 1536 + gate * HDIM + jg);

        // gather h_s from tagged global words (tag == s)
        if (s > 0 && tid < 256) {
            const unsigned long long* p = hx + 2 * tid;
            unsigned tgt = (unsigned)s;
            unsigned long long v0, v1;
            for (;;) {
                asm volatile("ld.relaxed.gpu.global.b64 %0, [%1];" : "=l"(v0) : "l"(p) : "memory");
                asm volatile("ld.relaxed.gpu.global.b64 %0, [%1];" : "=l"(v1) : "l"(p + 1) : "memory");
                if ((unsigned)(v0 >> 32) == tgt && (unsigned)(v1 >> 32) == tgt) break;
            }
            h_sh[2 * tid] = __uint_as_float((unsigned)v0);
            h_sh[2 * tid + 1] = __uint_as_float((unsigned)v1);
        }
        __syncthreads();

        // partial dot over 32 h values
        float acc = 0.f;
        const float4* h4 = ((const float4*)h_sh) + lane * 8;
#pragma unroll
        for (int i = 0; i < 8; i++) {
            float4 hv = h4[i];
            acc = fmaf(w[i].x, hv.x, acc);
            acc = fmaf(w[i].y, hv.y, acc);
            acc = fmaf(w[i].z, hv.z, acc);
            acc = fmaf(w[i].w, hv.w, acc);
        }
        // reduce across the 16 lanes of this dot
        acc += __shfl_down_sync(0xffffffffu, acc, 8, 16);
        acc += __shfl_down_sync(0xffffffffu, acc, 4, 16);
        acc += __shfl_down_sync(0xffffffffu, acc, 2, 16);
        acc += __shfl_down_sync(0xffffffffu, acc, 1, 16);
        if (lane == 0) { s_sum[dot] = acc + myb; s_gi[dot] = giv; }
        __syncthreads();

        // gates + state update + tagged publish (8 threads)
        if (tid < GOUT) {
            float gr = s_gi[tid],      hr = s_sum[tid];
            float gz = s_gi[8 + tid],  hz = s_sum[8 + tid];
            float gn = s_gi[16 + tid], hn = s_sum[16 + tid];
            float r = 1.f / (1.f + __expf(-(gr + hr)));
            float z = 1.f / (1.f + __expf(-(gz + hz)));
            float x = gn + r * hn;
            float e = __expf(2.f * x);
            float n = 1.f - 2.f / (e + 1.f);   // tanh(x)
            float hnew = (1.f - z) * n + z * hprev;
            hprev = hnew;
            unsigned long long pv = ((unsigned long long)(unsigned)(s + 1) << 32)
                                  | (unsigned long long)__float_as_uint(hnew);
            asm volatile("st.relaxed.gpu.global.b64 [%0], %1;"
                         :: "l"(hx + jg - jl + tid), "l"(pv) : "memory");
            d_outcat[(size_t)t * 1024 + dir * HDIM + slice * GOUT + tid] = hnew;
        }
        // no extra sync: next-step h_sh writes are gated by the tag spin,
        // and s_sum/s_gi rewrites are gated by the next __syncthreads.
    }
}

// ---------------- KAN prep: cubic B-spline basis on efficient-kan extended grid ----------------
__device__ __forceinline__ void bspline8(float x, float* bs) {
    const float hstep = 2.0f / 5.0f;
    float g[12];
#pragma unroll
    for (int m = 0; m < 12; m++) g[m] = (float)(m - 3) * hstep - 1.0f;
    float b[11];
#pragma unroll
    for (int m = 0; m < 11; m++) b[m] = (x >= g[m] && x < g[m + 1]) ? 1.f : 0.f;
#pragma unroll
    for (int k = 1; k <= 3; k++) {
#pragma unroll
        for (int m = 0; m < 11 - k; m++) {
            b[m] = (x - g[m]) / (g[m + k] - g[m]) * b[m]
                 + (g[m + k + 1] - x) / (g[m + k + 1] - g[m + 1]) * b[m + 1];
        }
    }
#pragma unroll
    for (int m = 0; m < 8; m++) bs[m] = b[m];
}

// U[n] = [ silu(x[n,:]) | bases(x[n,0])... ] width = 9*inw
__global__ void prep_U_kernel(const float* __restrict__ X, float* __restrict__ U, int inw) {
    int idx = blockIdx.x * blockDim.x + threadIdx.x;
    int total = LSEQ * inw;
    if (idx >= total) return;
    int n = idx / inw, i = idx - n * inw;
    float x = X[idx];
    int uw = inw * 9;
    U[(size_t)n * uw + i] = x / (1.f + expf(-x));
    float bs[8];
    bspline8(x, bs);
    float4* d4 = (float4*)(U + (size_t)n * uw + inw + (size_t)i * 8);
    d4[0] = make_float4(bs[0], bs[1], bs[2], bs[3]);
    d4[1] = make_float4(bs[4], bs[5], bs[6], bs[7]);
}

// V[o] = [ base_w[o,:] | spline_w[o,:,:]*scaler[o,:] ]
__global__ void prep_V_kernel(const float* __restrict__ bw, const float* __restrict__ sw,
                              const float* __restrict__ sc, float* __restrict__ V, int inw) {
    int idx = blockIdx.x * blockDim.x + threadIdx.x;
    int total = HDIM * inw;
    if (idx >= total) return;
    int o = idx / inw, i = idx - o * inw;
    int uw = inw * 9;
    V[(size_t)o * uw + i] = bw[idx];
    float s = sc[idx];
    const float* swp = sw + (size_t)idx * 8;
    float4* d4 = (float4*)(V + (size_t)o * uw + inw + (size_t)i * 8);
    d4[0] = make_float4(swp[0] * s, swp[1] * s, swp[2] * s, swp[3] * s);
    d4[1] = make_float4(swp[4] * s, swp[5] * s, swp[6] * s, swp[7] * s);
}

// ---------------- y[o] = sum_n a2[n,o] * p[n] ----------------
__global__ void final_kernel(const float* __restrict__ p, float* __restrict__ y) {
    __shared__ float red[256];
    int o = blockIdx.x * 64 + (threadIdx.x & 63);
    int part = threadIdx.x >> 6;
    float acc = 0.f;
    for (int n = part; n < LSEQ; n += 4)
        acc += d_a2[(size_t)n * HDIM + o] * p[n];
    red[threadIdx.x] = acc;
    __syncthreads();
    if (part == 0)
        y[o] = red[threadIdx.x] + red[threadIdx.x + 64]
             + red[threadIdx.x + 128] + red[threadIdx.x + 192];
}

// ---------------- launch ----------------
extern "C" void kernel_launch(void* const* d_in, const int* in_sizes, int n_in,
                              void* d_out, int out_size) {
    const float* h    = (const float*)d_in[0];
    const float* p    = (const float*)d_in[1];
    const float* wihf = (const float*)d_in[2];
    const float* whhf = (const float*)d_in[3];
    const float* bihf = (const float*)d_in[4];
    const float* bhhf = (const float*)d_in[5];
    const float* wihb = (const float*)d_in[6];
    const float* whhb = (const float*)d_in[7];
    const float* bihb = (const float*)d_in[8];
    const float* bhhb = (const float*)d_in[9];
    const float* bw1  = (const float*)d_in[10];
    const float* sw1  = (const float*)d_in[11];
    const float* sc1  = (const float*)d_in[12];
    const float* bw2  = (const float*)d_in[13];
    const float* sw2  = (const float*)d_in[14];
    const float* sc2  = (const float*)d_in[15];

    float* out = (float*)d_out;
    float* y  = out;           // (512,)
    float* a1 = out + 512;     // (4096, 512)

    float *gi0, *oc, *u1, *v1, *u2, *v2;
    cudaGetSymbolAddress((void**)&gi0, d_gi);
    cudaGetSymbolAddress((void**)&oc,  d_outcat);
    cudaGetSymbolAddress((void**)&u1,  d_U1);
    cudaGetSymbolAddress((void**)&v1,  d_V1);
    cudaGetSymbolAddress((void**)&u2,  d_U2);
    cudaGetSymbolAddress((void**)&v2,  d_V2);
    float* a2;
    cudaGetSymbolAddress((void**)&a2,  d_a2);
    float* gi1 = gi0 + (size_t)LSEQ * 1536;

    init_kernel<<<1, 1024>>>();

    // input-gate GEMMs: gi = h @ w_ih^T + b_ih   (4096 x 1536, K=512)
    sgemm_kernel<<<dim3(1536 / 128, LSEQ / 128), 256>>>(h, wihf, bihf, gi0, LSEQ, 1536, 512, 0);
    sgemm_kernel<<<dim3(1536 / 128, LSEQ / 128), 256>>>(h, wihb, bihb, gi1, LSEQ, 1536, 512, 0);

    // persistent bidirectional recurrence
    gru_kernel<<<2 * GCTAS, GTH>>>(whhf, bhhf, whhb, bhhb);

    // KAN layer 1: a1 = relu(U1 @ V1^T), U1 = [silu | bases] of outcat (width 9216)
    prep_V_kernel<<<(HDIM * 1024 + 255) / 256, 256>>>(bw1, sw1, sc1, v1, 1024);
    prep_U_kernel<<<(LSEQ * 1024 + 255) / 256, 256>>>(oc, u1, 1024);
    sgemm_kernel<<<dim3(HDIM / 128, LSEQ / 128), 256>>>(u1, v1, nullptr, a1, LSEQ, HDIM, 9216, 1);

    // KAN layer 2: a2 = sigmoid(U2 @ V2^T), width 4608
    prep_V_kernel<<<(HDIM * 512 + 255) / 256, 256>>>(bw2, sw2, sc2, v2, 512);
    prep_U_kernel<<<(LSEQ * 512 + 255) / 256, 256>>>(a1, u2, 512);
    sgemm_kernel<<<dim3(HDIM / 128, LSEQ / 128), 256>>>(u2, v2, nullptr, a2, LSEQ, HDIM, 4608, 2);

    // y = a2^T @ p
    final_kernel<<<8, 256>>>(p, y);
}